// round 7
// baseline (speedup 1.0000x reference)
#include <cuda_runtime.h>
#include <cuda_fp16.h>
#include <math.h>
#include <stdint.h>

#define B_ 4
#define T_ 4096
#define D_ 1024
#define H_ 8
#define K_ 128
#define V_ 128
#define F_ 4096
#define M_ (B_*T_)   // 16384 rows

// ---------------- scratch (device globals) ----------------
__device__ __align__(128) __half g_nh[(size_t)M_*D_];
__device__ __align__(128) __half g_qh[(size_t)M_*H_*K_];
__device__ __align__(128) __half g_kh[(size_t)M_*H_*K_];
__device__ __align__(128) __half g_vh[(size_t)M_*H_*V_];
__device__ __align__(128) float g_al[(size_t)M_*H_];
__device__ __align__(128) float g_be[(size_t)M_*H_];
__device__ __align__(128) __half g_oh[(size_t)M_*H_*V_];
__device__ __align__(128) float g_x1[(size_t)M_*D_];
__device__ __align__(128) __half g_hh[(size_t)M_*D_];
__device__ __align__(128) __half g_fh[(size_t)M_*F_];
__device__ __align__(128) __half g_wq[1024*1024];
__device__ __align__(128) __half g_wk[1024*1024];
__device__ __align__(128) __half g_wv[1024*1024];
__device__ __align__(128) __half g_wo[1024*1024];
__device__ __align__(128) __half g_w1[(size_t)4096*1024];
__device__ __align__(128) __half g_w2[(size_t)1024*4096];

// ======================== PTX helpers ========================
__device__ __forceinline__ uint32_t smem_u32(const void* p) {
    uint32_t a;
    asm("{ .reg .u64 t; cvta.to.shared.u64 t, %1; cvt.u32.u64 %0, t; }" : "=r"(a) : "l"(p));
    return a;
}
__device__ __forceinline__ void cp16(uint32_t s, const void* g) {
    asm volatile("cp.async.cg.shared.global [%0], [%1], 16;\n" :: "r"(s), "l"(g));
}
__device__ __forceinline__ void cp_commit() { asm volatile("cp.async.commit_group;\n" ::: "memory"); }
template<int N> __device__ __forceinline__ void cp_wait() {
    asm volatile("cp.async.wait_group %0;\n" :: "n"(N) : "memory");
}
__device__ __forceinline__ void ldsm4(uint32_t& r0, uint32_t& r1, uint32_t& r2, uint32_t& r3, uint32_t addr) {
    asm volatile("ldmatrix.sync.aligned.m8n8.x4.shared.b16 {%0,%1,%2,%3}, [%4];"
        : "=r"(r0), "=r"(r1), "=r"(r2), "=r"(r3) : "r"(addr));
}
__device__ __forceinline__ void mma16816(float* d, const uint32_t* a, const uint32_t* b) {
    asm volatile("mma.sync.aligned.m16n8k16.row.col.f32.f16.f16.f32 "
        "{%0,%1,%2,%3},{%4,%5,%6,%7},{%8,%9},{%0,%1,%2,%3};"
        : "+f"(d[0]), "+f"(d[1]), "+f"(d[2]), "+f"(d[3])
        : "r"(a[0]), "r"(a[1]), "r"(a[2]), "r"(a[3]), "r"(b[0]), "r"(b[1]));
}
__device__ __forceinline__ float silu_f(float x) {
    return x / (1.f + __expf(-x));
}

// ======================== HMMA GEMM ========================
// C[M,N] = A[M,Kd] @ W[Kd,N]; A fp16 [M,Kd]; B transposed fp16 [N,Kd].
// Block tile 256x128, 8 warps (4m x 2n), warp tile 64x64. K chunks of 64.
// 4-stage cp.async ring, lookahead 2, ONE barrier per chunk.
// Smem rows 144B (128B data + 16B pad): ldmatrix 8-row phases conflict-free.
// EPI: 0=fp32, 1=+resid fp32, 2=+bias+GELU->fp16, 3=+bias+resid fp32,
//      4=silu+l2norm->fp16 (per-head, N tile==head), 5=silu->fp16
#define TMM 256
#define TNN 128
#define KC 64
#define ROWB 144
#define ARR_A (TMM*ROWB)            // 36864
#define ARR_Bw (TNN*ROWB)           // 18432
#define STG_B (ARR_A + ARR_Bw)      // 55296
#define NSTAGE 4
#define DSMEM_SZ (NSTAGE*STG_B + 1024)   // 222208

template<int EPI>
__global__ __launch_bounds__(256, 1) void tc_gemm(
    const __half* __restrict__ A, const __half* __restrict__ Bw,
    const float* __restrict__ bias, const float* __restrict__ resid,
    float* __restrict__ C, __half* __restrict__ Ch,
    int M, int N, int Kd)
{
    extern __shared__ __align__(1024) char dsm_raw[];
    const int tid = threadIdx.x;
    const int wid = tid >> 5, lane = tid & 31;
    const int row0 = blockIdx.y * TMM;
    const int col0 = blockIdx.x * TNN;
    const int NC = Kd / KC;

    uint32_t sbase = smem_u32(dsm_raw);
    sbase = (sbase + 1023) & ~1023u;

    const int wm0 = (wid >> 1) * 64;
    const int wn0 = (wid & 1) * 64;

    float acc[4][8][4];
    #pragma unroll
    for (int i = 0; i < 4; i++)
        #pragma unroll
        for (int j = 0; j < 8; j++)
            #pragma unroll
            for (int r = 0; r < 4; r++) acc[i][j][r] = 0.f;

    auto load_chunk = [&](int c) {
        const int kb = c * KC;
        const uint32_t sb = sbase + (c % NSTAGE) * STG_B;
        #pragma unroll
        for (int i = 0; i < 8; i++) {                 // A: 256 rows x 8 segs
            int idx = tid + i * 256;
            int row = idx >> 3, seg = idx & 7;
            cp16(sb + row * ROWB + seg * 16,
                 A + (size_t)(row0 + row) * Kd + kb + seg * 8);
        }
        #pragma unroll
        for (int i = 0; i < 4; i++) {                 // B: 128 rows x 8 segs
            int idx = tid + i * 256;
            int row = idx >> 3, seg = idx & 7;
            cp16(sb + ARR_A + row * ROWB + seg * 16,
                 Bw + (size_t)(col0 + row) * Kd + kb + seg * 8);
        }
        cp_commit();
    };

    load_chunk(0);
    load_chunk(1);

    const int sub = lane >> 3, r8 = lane & 7;

    for (int c = 0; c < NC; c++) {
        if (c + 2 < NC) { load_chunk(c + 2); cp_wait<2>(); }
        else if (c + 2 == NC) cp_wait<1>();
        else cp_wait<0>();
        __syncthreads();

        const uint32_t sb = sbase + (c % NSTAGE) * STG_B;
        #pragma unroll
        for (int kk = 0; kk < 4; kk++) {              // four k16 steps
            const int kbyte = kk * 32;
            uint32_t af[4][4];
            #pragma unroll
            for (int mi = 0; mi < 4; mi++) {
                int row = wm0 + mi * 16 + (sub & 1) * 8 + r8;
                uint32_t off = row * ROWB + kbyte + (sub >> 1) * 16;
                ldsm4(af[mi][0], af[mi][1], af[mi][2], af[mi][3], sb + off);
            }
            uint32_t bf[8][2];
            #pragma unroll
            for (int nj = 0; nj < 4; nj++) {
                int row = wn0 + nj * 16 + (sub >> 1) * 8 + r8;
                uint32_t off = row * ROWB + kbyte + (sub & 1) * 16;
                ldsm4(bf[nj*2][0], bf[nj*2][1], bf[nj*2+1][0], bf[nj*2+1][1],
                      sb + ARR_A + off);
            }
            #pragma unroll
            for (int mi = 0; mi < 4; mi++)
                #pragma unroll
                for (int ni = 0; ni < 8; ni++)
                    mma16816(acc[mi][ni], af[mi], bf[ni]);
        }
        // no trailing barrier: 4-stage ring + lookahead 2 keeps writer
        // slot (c+2)%4 disjoint from reader slots {c-1, c}%4.
    }

    // ---------------- epilogue ----------------
    const int bcol0 = col0 + wn0;
    if (EPI == 4) {
        // pass 1: silu in place + per-row sum of squares
        __syncthreads();
        float* s2buf = (float*)dsm_raw;   // [2][TMM]
        #pragma unroll
        for (int mi = 0; mi < 4; mi++) {
            #pragma unroll
            for (int hf = 0; hf < 2; hf++) {
                const int rowl = wm0 + mi * 16 + hf * 8 + (lane >> 2);
                float s2 = 0.f;
                #pragma unroll
                for (int ni = 0; ni < 8; ni++) {
                    float s0 = silu_f(acc[mi][ni][hf*2]);
                    float s1 = silu_f(acc[mi][ni][hf*2+1]);
                    acc[mi][ni][hf*2] = s0; acc[mi][ni][hf*2+1] = s1;
                    s2 += s0*s0 + s1*s1;
                }
                s2 += __shfl_xor_sync(~0u, s2, 1);
                s2 += __shfl_xor_sync(~0u, s2, 2);
                if ((lane & 3) == 0) s2buf[(wid & 1) * TMM + rowl] = s2;
            }
        }
        __syncthreads();
        #pragma unroll
        for (int mi = 0; mi < 4; mi++) {
            #pragma unroll
            for (int hf = 0; hf < 2; hf++) {
                const int rowl = wm0 + mi * 16 + hf * 8 + (lane >> 2);
                const int row = row0 + rowl;
                float inv = rsqrtf(s2buf[rowl] + s2buf[TMM + rowl] + 1e-6f);
                #pragma unroll
                for (int ni = 0; ni < 8; ni++) {
                    const int col = bcol0 + ni * 8 + (lane & 3) * 2;
                    __half2 hh(__float2half_rn(acc[mi][ni][hf*2] * inv),
                               __float2half_rn(acc[mi][ni][hf*2+1] * inv));
                    *(uint32_t*)(Ch + (size_t)row * N + col) = *(uint32_t*)&hh;
                }
            }
        }
        return;
    }

    float2 bv[8];
    if (EPI == 2 || EPI == 3) {
        #pragma unroll
        for (int ni = 0; ni < 8; ni++)
            bv[ni] = *(const float2*)(bias + bcol0 + ni * 8 + (lane & 3) * 2);
    }
    #pragma unroll
    for (int mi = 0; mi < 4; mi++) {
        #pragma unroll
        for (int hf = 0; hf < 2; hf++) {
            const int row = row0 + wm0 + mi * 16 + hf * 8 + (lane >> 2);
            #pragma unroll
            for (int ni = 0; ni < 8; ni++) {
                const int col = bcol0 + ni * 8 + (lane & 3) * 2;
                float y0 = acc[mi][ni][hf*2];
                float y1 = acc[mi][ni][hf*2+1];
                if (EPI == 2 || EPI == 3) { y0 += bv[ni].x; y1 += bv[ni].y; }
                if (EPI == 2) {
                    y0 = 0.5f*y0*(1.f + erff(y0*0.70710678118f));
                    y1 = 0.5f*y1*(1.f + erff(y1*0.70710678118f));
                }
                if (EPI == 5) { y0 = silu_f(y0); y1 = silu_f(y1); }
                if (EPI == 1 || EPI == 3) {
                    float2 rv = *(const float2*)(resid + (size_t)row * N + col);
                    y0 += rv.x; y1 += rv.y;
                }
                if (EPI == 2 || EPI == 5) {
                    __half2 hh(__float2half_rn(y0), __float2half_rn(y1));
                    *(uint32_t*)(Ch + (size_t)row * N + col) = *(uint32_t*)&hh;
                } else {
                    *(float2*)(C + (size_t)row * N + col) = make_float2(y0, y1);
                }
            }
        }
    }
}

// ---------------- LayerNorm -> fp16 ----------------
__global__ __launch_bounds__(256) void ln_kernel(const float* __restrict__ x,
    const float* __restrict__ w, const float* __restrict__ bb,
    __half* __restrict__ oh)
{
    __shared__ float rs[8], rs2[8];
    int row = blockIdx.x, tid = threadIdx.x;
    const float4* xr = (const float4*)(x + (size_t)row * D_);
    float4 v = xr[tid];
    float s  = v.x + v.y + v.z + v.w;
    float s2 = v.x*v.x + v.y*v.y + v.z*v.z + v.w*v.w;
    #pragma unroll
    for (int m = 16; m; m >>= 1) {
        s  += __shfl_xor_sync(~0u, s,  m);
        s2 += __shfl_xor_sync(~0u, s2, m);
    }
    if ((tid & 31) == 0) { rs[tid>>5] = s; rs2[tid>>5] = s2; }
    __syncthreads();
    s = 0.f; s2 = 0.f;
    #pragma unroll
    for (int i = 0; i < 8; i++) { s += rs[i]; s2 += rs2[i]; }
    float mean = s * (1.0f/D_);
    float var  = s2 * (1.0f/D_) - mean*mean;
    float inv  = rsqrtf(var + 1e-5f);
    float4 wv = ((const float4*)w)[tid];
    float4 bv = ((const float4*)bb)[tid];
    float o0 = (v.x-mean)*inv*wv.x + bv.x;
    float o1 = (v.y-mean)*inv*wv.y + bv.y;
    float o2 = (v.z-mean)*inv*wv.z + bv.z;
    float o3 = (v.w-mean)*inv*wv.w + bv.w;
    __half2 h0(__float2half_rn(o0), __float2half_rn(o1));
    __half2 h1(__float2half_rn(o2), __float2half_rn(o3));
    ((uint2*)(oh + (size_t)row * D_))[tid] = make_uint2(*(uint32_t*)&h0, *(uint32_t*)&h1);
}

// ---------------- weight transpose: W[K,N] fp32 -> [N,K] fp16 ----------------
__global__ __launch_bounds__(256) void wconvT(const float* __restrict__ W,
    __half* __restrict__ WT, int Kd, int N)
{
    __shared__ float t[32][33];
    int n0 = blockIdx.x * 32, k0 = blockIdx.y * 32;
    int tx = threadIdx.x & 31, ty = threadIdx.x >> 5;
    #pragma unroll
    for (int i = 0; i < 4; i++)
        t[ty + 8*i][tx] = W[(size_t)(k0 + ty + 8*i) * N + n0 + tx];
    __syncthreads();
    #pragma unroll
    for (int i = 0; i < 4; i++)
        WT[(size_t)(n0 + ty + 8*i) * Kd + k0 + tx] = __float2half_rn(t[tx][ty + 8*i]);
}

// ---------------- alpha/beta: sigmoid(n @ W{a,b}) ----------------
__global__ __launch_bounds__(128) void ab_kernel(const __half* __restrict__ n,
    const float* __restrict__ Wb, const float* __restrict__ Wa,
    float* __restrict__ al, float* __restrict__ be)
{
    int row = blockIdx.x, tid = threadIdx.x;
    int g = tid >> 3, l = tid & 7;
    const float* W = (g < 8) ? Wb : Wa;
    int c = g & 7;
    const __half* nr = n + (size_t)row * D_;
    float s = 0.f;
    for (int d = l; d < D_; d += 8) s = fmaf(__half2float(nr[d]), W[d*H_ + c], s);
    s += __shfl_xor_sync(~0u, s, 1);
    s += __shfl_xor_sync(~0u, s, 2);
    s += __shfl_xor_sync(~0u, s, 4);
    if (l == 0) {
        float sig = 1.f/(1.f + __expf(-s));
        if (g < 8) be[(size_t)row*H_ + c] = sig;
        else       al[(size_t)row*H_ + c] = sig;
    }
}

// ---------------- gated delta-rule recurrence ----------------
// grid = 128 blocks (one (b,h) x 4 V-splits). 256 threads: col = tid>>3 (32
// cols), r8 = tid&7 (16 rows each). fp16 in/out, state fp32 in regs.
// k/q staged fp32 in smem, 3 buffers, skewed 20-float segments (conflict-free).
__global__ __launch_bounds__(256) void recur_kernel(
    const __half* __restrict__ q, const __half* __restrict__ k, const __half* __restrict__ v,
    const float* __restrict__ al, const float* __restrict__ be, __half* __restrict__ o)
{
    __shared__ __align__(16) float sk[3][160];
    __shared__ __align__(16) float sq[3][160];
    __shared__ float sv[3][32];
    __shared__ float sab[3][2];

    int blk = blockIdx.x;
    int bh = blk >> 2, split = blk & 3;
    int b = bh >> 3, h = bh & 7;
    int tid = threadIdx.x;
    int col = tid >> 3, r8 = tid & 7;
    int rbase = r8 * 20;
    int e = tid & 127;
    int sidx = (e >> 4) * 20 + (e & 15);
    size_t base  = ((size_t)b * T_ * H_ + h) * (size_t)K_;
    size_t abase = ((size_t)b * T_) * H_ + h;

    float S[16];
    #pragma unroll
    for (int i = 0; i < 16; i++) S[i] = 0.f;

    // stage t=0 into buffer 0
    if (tid < 128) sk[0][sidx] = __half2float(k[base + e]);
    else           sq[0][sidx] = __half2float(q[base + e]);
    if (tid < 32)  sv[0][tid] = __half2float(v[base + split*32 + tid]);
    if (tid == 0) { sab[0][0] = al[abase]; sab[0][1] = be[abase]; }
    __syncthreads();

    int bufc = 0;
    for (int t = 0; t < T_; t++) {
        int bufn = bufc + 1; if (bufn == 3) bufn = 0;
        // prefetch t+1
        float pkq = 0.f, pv = 0.f, pa = 0.f, pb = 0.f;
        if (t + 1 < T_) {
            size_t off = base + (size_t)(t+1) * (H_*K_);
            pkq = __half2float((tid < 128) ? k[off + e] : q[off + e]);
            if (tid < 32) pv = __half2float(v[off + split*32 + tid]);
            if (tid == 0) {
                pa = al[abase + (size_t)(t+1)*H_];
                pb = be[abase + (size_t)(t+1)*H_];
            }
        }
        // kv = k . S over this thread's 16 rows
        float kreg[16];
        float kv0 = 0.f, kv1 = 0.f, kv2 = 0.f, kv3 = 0.f;
        #pragma unroll
        for (int i4 = 0; i4 < 4; i4++) {
            float4 k4 = *(const float4*)(&sk[bufc][rbase + i4*4]);
            kreg[i4*4+0] = k4.x; kreg[i4*4+1] = k4.y;
            kreg[i4*4+2] = k4.z; kreg[i4*4+3] = k4.w;
            kv0 = fmaf(k4.x, S[i4*4+0], kv0);
            kv1 = fmaf(k4.y, S[i4*4+1], kv1);
            kv2 = fmaf(k4.z, S[i4*4+2], kv2);
            kv3 = fmaf(k4.w, S[i4*4+3], kv3);
        }
        float kv = (kv0+kv1)+(kv2+kv3);
        kv += __shfl_xor_sync(~0u, kv, 1);
        kv += __shfl_xor_sync(~0u, kv, 2);
        kv += __shfl_xor_sync(~0u, kv, 4);
        float a  = sab[bufc][0], bt = sab[bufc][1];
        float w  = bt * (sv[bufc][col] - a * kv);
        #pragma unroll
        for (int i = 0; i < 16; i++) S[i] = fmaf(a, S[i], kreg[i]*w);
        // stage t+1 into bufn (sq[bufc] still needed below — distinct buffer)
        if (t + 1 < T_) {
            if (tid < 128) sk[bufn][sidx] = pkq;
            else           sq[bufn][sidx] = pkq;
            if (tid < 32)  sv[bufn][tid] = pv;
            if (tid == 0) { sab[bufn][0] = pa; sab[bufn][1] = pb; }
        }
        __syncthreads();
        // o = q . S (post-update) — overlaps with next step's front
        float o0 = 0.f, o1 = 0.f, o2 = 0.f, o3 = 0.f;
        #pragma unroll
        for (int i4 = 0; i4 < 4; i4++) {
            float4 q4 = *(const float4*)(&sq[bufc][rbase + i4*4]);
            o0 = fmaf(q4.x, S[i4*4+0], o0);
            o1 = fmaf(q4.y, S[i4*4+1], o1);
            o2 = fmaf(q4.z, S[i4*4+2], o2);
            o3 = fmaf(q4.w, S[i4*4+3], o3);
        }
        float oa = (o0+o1)+(o2+o3);
        oa += __shfl_xor_sync(~0u, oa, 1);
        oa += __shfl_xor_sync(~0u, oa, 2);
        oa += __shfl_xor_sync(~0u, oa, 4);
        if (r8 == 0) o[base + (size_t)t*(H_*K_) + split*32 + col] = __float2half(oa);
        bufc = bufn;
    }
}

// ---------------- launch ----------------
extern "C" void kernel_launch(void* const* d_in, const int* in_sizes, int n_in,
                              void* d_out, int out_size)
{
    const float* x    = (const float*)d_in[0];
    const float* Wq   = (const float*)d_in[1];
    const float* Wk   = (const float*)d_in[2];
    const float* Wv   = (const float*)d_in[3];
    const float* Wb   = (const float*)d_in[4];
    const float* Wa   = (const float*)d_in[5];
    const float* Wo   = (const float*)d_in[6];
    const float* ln1w = (const float*)d_in[7];
    const float* ln1b = (const float*)d_in[8];
    const float* ln2w = (const float*)d_in[9];
    const float* ln2b = (const float*)d_in[10];
    const float* W1   = (const float*)d_in[11];
    const float* b1   = (const float*)d_in[12];
    const float* W2   = (const float*)d_in[13];
    const float* b2   = (const float*)d_in[14];
    float* out = (float*)d_out;

    float *al_, *be_, *x1_;
    __half *nh, *qh, *kh, *vh, *oh, *hh, *fh, *wq, *wk, *wv, *wo, *w1, *w2;
    cudaGetSymbolAddress((void**)&nh,  g_nh);
    cudaGetSymbolAddress((void**)&qh,  g_qh);
    cudaGetSymbolAddress((void**)&kh,  g_kh);
    cudaGetSymbolAddress((void**)&vh,  g_vh);
    cudaGetSymbolAddress((void**)&al_, g_al);
    cudaGetSymbolAddress((void**)&be_, g_be);
    cudaGetSymbolAddress((void**)&oh,  g_oh);
    cudaGetSymbolAddress((void**)&x1_, g_x1);
    cudaGetSymbolAddress((void**)&hh,  g_hh);
    cudaGetSymbolAddress((void**)&fh,  g_fh);
    cudaGetSymbolAddress((void**)&wq,  g_wq);
    cudaGetSymbolAddress((void**)&wk,  g_wk);
    cudaGetSymbolAddress((void**)&wv,  g_wv);
    cudaGetSymbolAddress((void**)&wo,  g_wo);
    cudaGetSymbolAddress((void**)&w1,  g_w1);
    cudaGetSymbolAddress((void**)&w2,  g_w2);

    cudaFuncSetAttribute(tc_gemm<1>, cudaFuncAttributeMaxDynamicSharedMemorySize, DSMEM_SZ);
    cudaFuncSetAttribute(tc_gemm<2>, cudaFuncAttributeMaxDynamicSharedMemorySize, DSMEM_SZ);
    cudaFuncSetAttribute(tc_gemm<3>, cudaFuncAttributeMaxDynamicSharedMemorySize, DSMEM_SZ);
    cudaFuncSetAttribute(tc_gemm<4>, cudaFuncAttributeMaxDynamicSharedMemorySize, DSMEM_SZ);
    cudaFuncSetAttribute(tc_gemm<5>, cudaFuncAttributeMaxDynamicSharedMemorySize, DSMEM_SZ);

    // weight transpose + fp16 convert
    wconvT<<<dim3(1024/32, 1024/32), 256>>>(Wq, wq, 1024, 1024);
    wconvT<<<dim3(1024/32, 1024/32), 256>>>(Wk, wk, 1024, 1024);
    wconvT<<<dim3(1024/32, 1024/32), 256>>>(Wv, wv, 1024, 1024);
    wconvT<<<dim3(1024/32, 1024/32), 256>>>(Wo, wo, 1024, 1024);
    wconvT<<<dim3(4096/32, 1024/32), 256>>>(W1, w1, 1024, 4096);
    wconvT<<<dim3(1024/32, 4096/32), 256>>>(W2, w2, 4096, 1024);

    // 1. ln1 -> fp16
    ln_kernel<<<M_, 256>>>(x, ln1w, ln1b, nh);

    // 2-4. q/k/v projections with fused activations (fp16 out)
    dim3 g1(1024/TNN, M_/TMM);   // (8, 64)
    tc_gemm<4><<<g1, 256, DSMEM_SZ>>>(nh, wq, nullptr, nullptr, nullptr, qh, M_, 1024, 1024);
    tc_gemm<4><<<g1, 256, DSMEM_SZ>>>(nh, wk, nullptr, nullptr, nullptr, kh, M_, 1024, 1024);
    tc_gemm<5><<<g1, 256, DSMEM_SZ>>>(nh, wv, nullptr, nullptr, nullptr, vh, M_, 1024, 1024);

    // 5. alpha/beta
    ab_kernel<<<M_, 128>>>(nh, Wb, Wa, al_, be_);

    // 6. recurrence (fp16 in/out)
    recur_kernel<<<B_*H_*4, 256>>>(qh, kh, vh, al_, be_, oh);

    // 7. output projection + residual (fp32 out)
    tc_gemm<1><<<g1, 256, DSMEM_SZ>>>(oh, wo, nullptr, x, x1_, nullptr, M_, 1024, 1024);

    // 8. ln2 -> fp16
    ln_kernel<<<M_, 256>>>(x1_, ln2w, ln2b, hh);

    // 9. FFN up: +bias, GELU -> fp16
    dim3 g2(4096/TNN, M_/TMM);   // (32, 64)
    tc_gemm<2><<<g2, 256, DSMEM_SZ>>>(hh, w1, b1, nullptr, nullptr, fh, M_, 4096, 1024);

    // 10. FFN down: +bias +resid -> fp32 out
    tc_gemm<3><<<g1, 256, DSMEM_SZ>>>(fh, w2, b2, x1_, out, nullptr, M_, 1024, 4096);
}